// round 1
// baseline (speedup 1.0000x reference)
#include <cuda_runtime.h>
#include <math.h>

#define BB   32
#define MM   16384
#define WW   256
#define HH   16
#define EPS  1e-5f

#define MT   256          // rows per block
#define KC   32           // K chunk (columns per smem tile)
#define NCH  (WW / KC)    // 8 chunks
#define RP   260          // memT row pitch (floats), multiple of 4

// smem layout (floats)
#define OFF_MEMT   0                       // [KC][RP]  = 8320
#define OFF_KEYSD  (OFF_MEMT + KC * RP)    // [WW][32]  = 8192 (heads duplicated)
#define OFF_SHARP  (OFF_KEYSD + WW * 32)   // [HH][MT]  = 4096
#define OFF_ROWSS  (OFF_SHARP + HH * MT)   // [MT]      = 256
#define OFF_KN     (OFF_ROWSS + MT)        // [HH]
#define OFF_SP     (OFF_KN + HH)           // [HH]
#define SMEM_FLOATS (OFF_SP + HH)
#define SMEM_BYTES  (SMEM_FLOATS * 4)

__device__ __forceinline__ void fma2(unsigned long long& acc,
                                     unsigned long long a,
                                     unsigned long long b) {
    asm("fma.rn.f32x2 %0, %1, %2, %0;" : "+l"(acc) : "l"(a), "l"(b));
}

__device__ __forceinline__ float lo32(unsigned long long v) {
    return __uint_as_float((unsigned)(v & 0xffffffffull));
}
__device__ __forceinline__ float hi32(unsigned long long v) {
    return __uint_as_float((unsigned)(v >> 32));
}

__device__ __forceinline__ float softplus_f(float x) {
    // log1p(exp(x)) stable
    return fmaxf(x, 0.0f) + log1pf(__expf(-fabsf(x)));
}

__global__ void __launch_bounds__(256, 2)
pass1_kernel(const float* __restrict__ memory,
             const float* __restrict__ keys,
             const float* __restrict__ strengths,
             float* __restrict__ out) {
    extern __shared__ float sm[];
    float* memT   = sm + OFF_MEMT;    // [KC][RP] transposed tile: memT[k][r]
    float* keysD  = sm + OFF_KEYSD;   // [WW][32]: keysD[k][2h]=keysD[k][2h+1]=key[h][k]
    float* sharp  = sm + OFF_SHARP;   // [HH][MT]
    float* rowss  = sm + OFF_ROWSS;   // [MT]
    float* kn_sm  = sm + OFF_KN;
    float* sp_sm  = sm + OFF_SP;

    const int tid = threadIdx.x;
    const int b   = blockIdx.y;
    const int m0  = blockIdx.x * MT;

    // ---- prologue: fill keysD (duplicated heads) ----
    {
        const float4* kb4 = (const float4*)(keys + (size_t)b * HH * WW);
        #pragma unroll
        for (int i = 0; i < 4; i++) {
            int idx = tid + 256 * i;           // 1024 float4 total
            int h   = idx >> 6;                // /64
            int k4  = idx & 63;
            float4 v = kb4[idx];
            float vv[4] = {v.x, v.y, v.z, v.w};
            #pragma unroll
            for (int j = 0; j < 4; j++) {
                int k = k4 * 4 + j;
                keysD[k * 32 + 2 * h]     = vv[j];
                keysD[k * 32 + 2 * h + 1] = vv[j];
            }
        }
    }
    __syncthreads();

    // ---- key norms + softplus(strength) ----
    {
        int h  = tid >> 4;       // 0..15
        int l16 = tid & 15;
        float ss = 0.0f;
        #pragma unroll
        for (int q = 0; q < 16; q++) {
            int k = l16 + 16 * q;
            float v = keysD[k * 32 + 2 * h];
            ss = fmaf(v, v, ss);
        }
        ss += __shfl_xor_sync(0xffffffffu, ss, 1);
        ss += __shfl_xor_sync(0xffffffffu, ss, 2);
        ss += __shfl_xor_sync(0xffffffffu, ss, 4);
        ss += __shfl_xor_sync(0xffffffffu, ss, 8);
        if (l16 == 0) {
            kn_sm[h] = sqrtf(ss + EPS);
            sp_sm[h] = softplus_f(strengths[b * HH + h]);
        }
    }

    // ---- main loop over K chunks ----
    const float4* gp = (const float4*)memory + ((size_t)b * MM + m0) * (WW / 4);
    const int rg = tid >> 2;   // 0..63 -> rows rg*4..rg*4+3
    const int hg = tid & 3;    // 0..3  -> heads hg*4..hg*4+3

    unsigned long long a00 = 0, a01 = 0, a10 = 0, a11 = 0;
    unsigned long long a20 = 0, a21 = 0, a30 = 0, a31 = 0;
    float ss_row = 0.0f;

    float4 pre[8];
    // prefetch chunk 0
    #pragma unroll
    for (int i = 0; i < 8; i++) {
        int idx = tid + 256 * i;
        int r = idx >> 3, c4 = idx & 7;
        pre[i] = gp[(size_t)r * (WW / 4) + c4];
    }

    for (int c = 0; c < NCH; c++) {
        __syncthreads();   // previous chunk's readers done
        // transposed store: memT[k][r]
        #pragma unroll
        for (int i = 0; i < 8; i++) {
            int idx = tid + 256 * i;
            int r = idx >> 3, c4 = idx & 7;
            float vv[4] = {pre[i].x, pre[i].y, pre[i].z, pre[i].w};
            #pragma unroll
            for (int j = 0; j < 4; j++)
                memT[(c4 * 4 + j) * RP + r] = vv[j];
        }
        __syncthreads();

        // prefetch next chunk (overlaps compute below)
        if (c + 1 < NCH) {
            #pragma unroll
            for (int i = 0; i < 8; i++) {
                int idx = tid + 256 * i;
                int r = idx >> 3, c4 = idx & 7;
                pre[i] = gp[(size_t)r * (WW / 4) + (c + 1) * 8 + c4];
            }
        }

        // row sum-of-squares (thread tid owns row tid), conflict-free strided LDS
        #pragma unroll 8
        for (int k = 0; k < KC; k++) {
            float v = memT[k * RP + tid];
            ss_row = fmaf(v, v, ss_row);
        }

        // dot products: 4 heads x 4 rows per thread via packed f32x2 FMA
        const float* kD = keysD + (size_t)(c * KC) * 32;
        #pragma unroll 8
        for (int k = 0; k < KC; k++) {
            longlong2 mv = *(const longlong2*)(memT + k * RP + (rg << 2));
            longlong2 k0 = *(const longlong2*)(kD + k * 32 + (hg << 3));
            longlong2 k1 = *(const longlong2*)(kD + k * 32 + (hg << 3) + 4);
            fma2(a00, k0.x, mv.x); fma2(a01, k0.x, mv.y);
            fma2(a10, k0.y, mv.x); fma2(a11, k0.y, mv.y);
            fma2(a20, k1.x, mv.x); fma2(a21, k1.x, mv.y);
            fma2(a30, k1.y, mv.x); fma2(a31, k1.y, mv.y);
        }
    }

    rowss[tid] = ss_row;
    __syncthreads();

    // ---- epilogue: sharpen and stage to smem ----
    {
        float mn[4];
        #pragma unroll
        for (int i = 0; i < 4; i++)
            mn[i] = sqrtf(rowss[(rg << 2) + i] + EPS);

        unsigned long long accs[4][2] = {{a00, a01}, {a10, a11}, {a20, a21}, {a30, a31}};
        #pragma unroll
        for (int j = 0; j < 4; j++) {
            int h = (hg << 2) + j;
            float spv = sp_sm[h];
            float knv = kn_sm[h];
            #pragma unroll
            for (int p = 0; p < 2; p++) {
                float dlo = lo32(accs[j][p]);
                float dhi = hi32(accs[j][p]);
                int r0 = (rg << 2) + 2 * p;
                sharp[h * MT + r0]     = __fdividef(dlo * spv, fmaf(knv, mn[2 * p], EPS));
                sharp[h * MT + r0 + 1] = __fdividef(dhi * spv, fmaf(knv, mn[2 * p + 1], EPS));
            }
        }
    }
    __syncthreads();

    // ---- coalesced write: out[b][h][m0 .. m0+MT) ----
    {
        float4* o4 = (float4*)out;
        #pragma unroll
        for (int i = 0; i < 4; i++) {
            int lin = i * 256 + tid;        // 1024 float4 total
            int h   = lin >> 6;
            int r4  = lin & 63;
            float4 v = *(const float4*)(sharp + h * MT + r4 * 4);
            o4[(((size_t)b * HH + h) * MM + m0) / 4 + r4] = v;
        }
    }
}

// ---- pass 2: in-place softmax over M per (b,h) row ----
__global__ void __launch_bounds__(1024)
softmax_kernel(float* __restrict__ out) {
    const int row = blockIdx.x;            // b*H + h
    float4* p4 = (float4*)(out + (size_t)row * MM);
    const int t = threadIdx.x;
    const int lane = t & 31, wid = t >> 5;

    __shared__ float sdata[32];
    __shared__ float sres;

    float v[16];
    float lmax = -INFINITY;
    #pragma unroll
    for (int i = 0; i < 4; i++) {
        float4 x = p4[t + 1024 * i];
        v[i * 4 + 0] = x.x; v[i * 4 + 1] = x.y;
        v[i * 4 + 2] = x.z; v[i * 4 + 3] = x.w;
        lmax = fmaxf(lmax, fmaxf(fmaxf(x.x, x.y), fmaxf(x.z, x.w)));
    }
    // block max
    #pragma unroll
    for (int o = 16; o; o >>= 1) lmax = fmaxf(lmax, __shfl_xor_sync(0xffffffffu, lmax, o));
    if (lane == 0) sdata[wid] = lmax;
    __syncthreads();
    if (wid == 0) {
        float x = sdata[lane];
        #pragma unroll
        for (int o = 16; o; o >>= 1) x = fmaxf(x, __shfl_xor_sync(0xffffffffu, x, o));
        if (lane == 0) sres = x;
    }
    __syncthreads();
    float gmax = sres;
    __syncthreads();

    float lsum = 0.0f;
    #pragma unroll
    for (int i = 0; i < 16; i++) {
        float e = __expf(v[i] - gmax);
        v[i] = e;
        lsum += e;
    }
    #pragma unroll
    for (int o = 16; o; o >>= 1) lsum += __shfl_xor_sync(0xffffffffu, lsum, o);
    if (lane == 0) sdata[wid] = lsum;
    __syncthreads();
    if (wid == 0) {
        float x = sdata[lane];
        #pragma unroll
        for (int o = 16; o; o >>= 1) x += __shfl_xor_sync(0xffffffffu, x, o);
        if (lane == 0) sres = x;
    }
    __syncthreads();
    float inv = __fdividef(1.0f, sres);

    #pragma unroll
    for (int i = 0; i < 4; i++) {
        float4 x;
        x.x = v[i * 4 + 0] * inv; x.y = v[i * 4 + 1] * inv;
        x.z = v[i * 4 + 2] * inv; x.w = v[i * 4 + 3] * inv;
        p4[t + 1024 * i] = x;
    }
}

extern "C" void kernel_launch(void* const* d_in, const int* in_sizes, int n_in,
                              void* d_out, int out_size) {
    const float* memory    = (const float*)d_in[0];
    const float* keys      = (const float*)d_in[1];
    const float* strengths = (const float*)d_in[2];
    float* out = (float*)d_out;

    cudaFuncSetAttribute(pass1_kernel,
                         cudaFuncAttributeMaxDynamicSharedMemorySize, SMEM_BYTES);

    dim3 grid1(MM / MT, BB);
    pass1_kernel<<<grid1, 256, SMEM_BYTES>>>(memory, keys, strengths, out);
    softmax_kernel<<<BB * HH, 1024>>>(out);
}

// round 2
// speedup vs baseline: 1.6634x; 1.6634x over previous
#include <cuda_runtime.h>
#include <math.h>
#include <stdint.h>

#define BB   32
#define MM   16384
#define WW   256
#define HH   16
#define EPS  1e-5f

#define MT    256            // rows per block
#define KC    32             // K floats per chunk
#define NCH   (WW / KC)      // 8 chunks
#define PITCH 36             // tile row pitch in floats (144B = 16 mod 128 -> bank spread)

// smem byte layout
#define SMEM_BUF0   0
#define SMEM_BUF1   36864                     // 256*36*4
#define SMEM_KEYS   73728                     // [64 k4][16 h] float4 = 16384B
#define SMEM_SS     (SMEM_KEYS + 16384)       // 256 floats = 1024B
#define SMEM_KN     (SMEM_SS + 1024)          // 16 floats
#define SMEM_SP     (SMEM_KN + 64)            // 16 floats
#define SMEM_TOTAL  (SMEM_SP + 64)
// sharp buffer (16 x 264 floats = 16896B) overlays BUF0 in the epilogue
#define SHARP_PITCH 264

__device__ __forceinline__ void fma2(unsigned long long& acc,
                                     unsigned long long a,
                                     unsigned long long b) {
    asm("fma.rn.f32x2 %0, %1, %2, %0;" : "+l"(acc) : "l"(a), "l"(b));
}
__device__ __forceinline__ float lo32(unsigned long long v) {
    return __uint_as_float((unsigned)(v & 0xffffffffull));
}
__device__ __forceinline__ float hi32(unsigned long long v) {
    return __uint_as_float((unsigned)(v >> 32));
}
__device__ __forceinline__ void cp_async16(unsigned smem_addr, const void* gptr) {
    asm volatile("cp.async.cg.shared.global [%0], [%1], 16;\n"
                 :: "r"(smem_addr), "l"(gptr));
}
__device__ __forceinline__ void cp_commit() {
    asm volatile("cp.async.commit_group;\n");
}
template <int N>
__device__ __forceinline__ void cp_wait() {
    asm volatile("cp.async.wait_group %0;\n" :: "n"(N));
}
__device__ __forceinline__ float softplus_f(float x) {
    return fmaxf(x, 0.0f) + log1pf(__expf(-fabsf(x)));
}

__global__ void __launch_bounds__(256, 2)
pass1_kernel(const float* __restrict__ memory,
             const float* __restrict__ keys,
             const float* __restrict__ strengths,
             float* __restrict__ out) {
    extern __shared__ char sm[];
    float* smf = (float*)sm;
    unsigned smem_base;
    asm("{ .reg .u64 t; cvta.to.shared.u64 t, %1; cvt.u32.u64 %0, t; }"
        : "=r"(smem_base) : "l"(sm));

    const int tid  = threadIdx.x;
    const int b    = blockIdx.y;
    const int m0   = blockIdx.x * MT;
    const int lane = tid & 31;
    const int w    = tid >> 5;

    const float* gmem = memory + ((size_t)b * MM + m0) * WW;

    // ---- start chunk 0 and 1 loads immediately ----
    {
        #pragma unroll
        for (int u = 0; u < 8; u++) {
            int f  = tid + 256 * u;
            int r  = f >> 3, c4 = f & 7;
            cp_async16(smem_base + SMEM_BUF0 + r * (PITCH * 4) + c4 * 16,
                       gmem + (size_t)r * WW + c4 * 4);
        }
        cp_commit();
        #pragma unroll
        for (int u = 0; u < 8; u++) {
            int f  = tid + 256 * u;
            int r  = f >> 3, c4 = f & 7;
            cp_async16(smem_base + SMEM_BUF1 + r * (PITCH * 4) + c4 * 16,
                       gmem + (size_t)r * WW + KC + c4 * 4);
        }
        cp_commit();
    }

    // ---- stage keys into [k4][h] float4 table ----
    {
        float* keysQ = smf + SMEM_KEYS / 4;
        const float4* kb = (const float4*)(keys + (size_t)b * HH * WW);
        #pragma unroll
        for (int u = 0; u < 4; u++) {
            int f  = tid + 256 * u;          // f = h*64 + k4
            int h  = f >> 6;
            int k4 = f & 63;
            *(float4*)(keysQ + (k4 * 16 + h) * 4) = kb[f];
        }
    }
    __syncthreads();

    // ---- key norms + softplus(strength) ----
    {
        const float* keysQ = smf + SMEM_KEYS / 4;
        int h   = tid >> 4;
        int l16 = tid & 15;
        float ss = 0.0f;
        #pragma unroll
        for (int q = 0; q < 16; q++) {
            int k = l16 + 16 * q;
            float v = keysQ[((k >> 2) * 16 + h) * 4 + (k & 3)];
            ss = fmaf(v, v, ss);
        }
        ss += __shfl_xor_sync(0xffffffffu, ss, 1);
        ss += __shfl_xor_sync(0xffffffffu, ss, 2);
        ss += __shfl_xor_sync(0xffffffffu, ss, 4);
        ss += __shfl_xor_sync(0xffffffffu, ss, 8);
        if (l16 == 0) {
            smf[SMEM_KN / 4 + h] = sqrtf(ss + EPS);
            smf[SMEM_SP / 4 + h] = softplus_f(strengths[b * HH + h]);
        }
    }

    // ---- main loop ----
    const int hg = tid & 3;   // heads hg, hg+4, hg+8, hg+12
    const int rG = tid >> 2;  // rows rG, rG+64, rG+128, rG+192

    unsigned long long acc[4][4];
    #pragma unroll
    for (int i = 0; i < 4; i++)
        #pragma unroll
        for (int j = 0; j < 4; j++) acc[i][j] = 0ull;

    unsigned long long ssp[4] = {0ull, 0ull, 0ull, 0ull};
    const int ssr = 8 * w + (lane >> 2);   // ss row base
    const int ssq = lane & 3;              // ss k-slot

    const float* keysQ = smf + SMEM_KEYS / 4;

    for (int c = 0; c < NCH; c++) {
        if (c < NCH - 1) cp_wait<1>(); else cp_wait<0>();
        __syncthreads();

        const float* buf = smf + ((c & 1) ? SMEM_BUF1 : SMEM_BUF0) / 4;

        // row sum-of-squares sweep (packed)
        #pragma unroll
        for (int rr = 0; rr < 4; rr++) {
            #pragma unroll
            for (int q = 0; q < 2; q++) {
                ulonglong2 v = *(const ulonglong2*)(buf + (ssr + 64 * rr) * PITCH
                                                    + (ssq + 4 * q) * 4);
                fma2(ssp[rr], v.x, v.x);
                fma2(ssp[rr], v.y, v.y);
            }
        }

        // dot products: 4 rows x 4 heads, packed even/odd-k partials
        #pragma unroll
        for (int k4 = 0; k4 < 8; k4++) {
            const float* kp = keysQ + ((c * 8 + k4) * 16 + hg) * 4;
            ulonglong2 kv0 = *(const ulonglong2*)(kp);
            ulonglong2 kv1 = *(const ulonglong2*)(kp + 16);
            ulonglong2 kv2 = *(const ulonglong2*)(kp + 32);
            ulonglong2 kv3 = *(const ulonglong2*)(kp + 48);

            ulonglong2 mv0 = *(const ulonglong2*)(buf + (rG)       * PITCH + k4 * 4);
            ulonglong2 mv1 = *(const ulonglong2*)(buf + (rG +  64) * PITCH + k4 * 4);
            ulonglong2 mv2 = *(const ulonglong2*)(buf + (rG + 128) * PITCH + k4 * 4);
            ulonglong2 mv3 = *(const ulonglong2*)(buf + (rG + 192) * PITCH + k4 * 4);

            fma2(acc[0][0], mv0.x, kv0.x); fma2(acc[0][0], mv0.y, kv0.y);
            fma2(acc[0][1], mv0.x, kv1.x); fma2(acc[0][1], mv0.y, kv1.y);
            fma2(acc[0][2], mv0.x, kv2.x); fma2(acc[0][2], mv0.y, kv2.y);
            fma2(acc[0][3], mv0.x, kv3.x); fma2(acc[0][3], mv0.y, kv3.y);

            fma2(acc[1][0], mv1.x, kv0.x); fma2(acc[1][0], mv1.y, kv0.y);
            fma2(acc[1][1], mv1.x, kv1.x); fma2(acc[1][1], mv1.y, kv1.y);
            fma2(acc[1][2], mv1.x, kv2.x); fma2(acc[1][2], mv1.y, kv2.y);
            fma2(acc[1][3], mv1.x, kv3.x); fma2(acc[1][3], mv1.y, kv3.y);

            fma2(acc[2][0], mv2.x, kv0.x); fma2(acc[2][0], mv2.y, kv0.y);
            fma2(acc[2][1], mv2.x, kv1.x); fma2(acc[2][1], mv2.y, kv1.y);
            fma2(acc[2][2], mv2.x, kv2.x); fma2(acc[2][2], mv2.y, kv2.y);
            fma2(acc[2][3], mv2.x, kv3.x); fma2(acc[2][3], mv2.y, kv3.y);

            fma2(acc[3][0], mv3.x, kv0.x); fma2(acc[3][0], mv3.y, kv0.y);
            fma2(acc[3][1], mv3.x, kv1.x); fma2(acc[3][1], mv3.y, kv1.y);
            fma2(acc[3][2], mv3.x, kv2.x); fma2(acc[3][2], mv3.y, kv2.y);
            fma2(acc[3][3], mv3.x, kv3.x); fma2(acc[3][3], mv3.y, kv3.y);
        }
        __syncthreads();

        // prefetch chunk c+2 into the buffer we just finished reading
        if (c + 2 < NCH) {
            unsigned dst = smem_base + (((c & 1) == 0) ? SMEM_BUF0 : SMEM_BUF1);
            #pragma unroll
            for (int u = 0; u < 8; u++) {
                int f  = tid + 256 * u;
                int r  = f >> 3, c4 = f & 7;
                cp_async16(dst + r * (PITCH * 4) + c4 * 16,
                           gmem + (size_t)r * WW + (c + 2) * KC + c4 * 4);
            }
            cp_commit();
        }
    }

    // ---- reduce row norms ----
    {
        #pragma unroll
        for (int rr = 0; rr < 4; rr++) {
            float s = lo32(ssp[rr]) + hi32(ssp[rr]);
            s += __shfl_xor_sync(0xffffffffu, s, 1);
            s += __shfl_xor_sync(0xffffffffu, s, 2);
            smf[SMEM_SS / 4 + ssr + 64 * rr] = s;  // 4 lanes write same value
        }
    }
    __syncthreads();

    // ---- epilogue: sharpen into smem (reuses BUF0), then coalesced write ----
    {
        float* sharp = smf + SMEM_BUF0 / 4;   // [16][SHARP_PITCH]
        float knv[4], spv[4];
        #pragma unroll
        for (int j = 0; j < 4; j++) {
            knv[j] = smf[SMEM_KN / 4 + hg + 4 * j];
            spv[j] = smf[SMEM_SP / 4 + hg + 4 * j];
        }
        #pragma unroll
        for (int i = 0; i < 4; i++) {
            int r = rG + 64 * i;
            float mn = sqrtf(smf[SMEM_SS / 4 + r] + EPS);
            #pragma unroll
            for (int j = 0; j < 4; j++) {
                float dot = lo32(acc[i][j]) + hi32(acc[i][j]);
                sharp[(hg + 4 * j) * SHARP_PITCH + r] =
                    __fdividef(dot * spv[j], fmaf(knv[j], mn, EPS));
            }
        }
    }
    __syncthreads();
    {
        const float* sharp = smf + SMEM_BUF0 / 4;
        float4* o4 = (float4*)out;
        #pragma unroll
        for (int u = 0; u < 4; u++) {
            int f  = tid + 256 * u;     // 1024 float4
            int h  = f >> 6;
            int r4 = f & 63;
            float4 v = *(const float4*)(sharp + h * SHARP_PITCH + r4 * 4);
            o4[(((size_t)b * HH + h) * MM + m0) / 4 + r4] = v;
        }
    }
}

// ---- pass 2: in-place softmax over M per (b,h) row ----
__global__ void __launch_bounds__(1024)
softmax_kernel(float* __restrict__ out) {
    const int row = blockIdx.x;            // b*H + h
    float4* p4 = (float4*)(out + (size_t)row * MM);
    const int t = threadIdx.x;
    const int lane = t & 31, wid = t >> 5;

    __shared__ float sdata[32];
    __shared__ float sres;

    float v[16];
    float lmax = -INFINITY;
    #pragma unroll
    for (int i = 0; i < 4; i++) {
        float4 x = p4[t + 1024 * i];
        v[i * 4 + 0] = x.x; v[i * 4 + 1] = x.y;
        v[i * 4 + 2] = x.z; v[i * 4 + 3] = x.w;
        lmax = fmaxf(lmax, fmaxf(fmaxf(x.x, x.y), fmaxf(x.z, x.w)));
    }
    #pragma unroll
    for (int o = 16; o; o >>= 1) lmax = fmaxf(lmax, __shfl_xor_sync(0xffffffffu, lmax, o));
    if (lane == 0) sdata[wid] = lmax;
    __syncthreads();
    if (wid == 0) {
        float x = sdata[lane];
        #pragma unroll
        for (int o = 16; o; o >>= 1) x = fmaxf(x, __shfl_xor_sync(0xffffffffu, x, o));
        if (lane == 0) sres = x;
    }
    __syncthreads();
    float gmax = sres;
    __syncthreads();

    float lsum = 0.0f;
    #pragma unroll
    for (int i = 0; i < 16; i++) {
        float e = __expf(v[i] - gmax);
        v[i] = e;
        lsum += e;
    }
    #pragma unroll
    for (int o = 16; o; o >>= 1) lsum += __shfl_xor_sync(0xffffffffu, lsum, o);
    if (lane == 0) sdata[wid] = lsum;
    __syncthreads();
    if (wid == 0) {
        float x = sdata[lane];
        #pragma unroll
        for (int o = 16; o; o >>= 1) x += __shfl_xor_sync(0xffffffffu, x, o);
        if (lane == 0) sres = x;
    }
    __syncthreads();
    float inv = __fdividef(1.0f, sres);

    #pragma unroll
    for (int i = 0; i < 4; i++) {
        float4 x;
        x.x = v[i * 4 + 0] * inv; x.y = v[i * 4 + 1] * inv;
        x.z = v[i * 4 + 2] * inv; x.w = v[i * 4 + 3] * inv;
        p4[t + 1024 * i] = x;
    }
}

extern "C" void kernel_launch(void* const* d_in, const int* in_sizes, int n_in,
                              void* d_out, int out_size) {
    const float* memory    = (const float*)d_in[0];
    const float* keys      = (const float*)d_in[1];
    const float* strengths = (const float*)d_in[2];
    float* out = (float*)d_out;

    cudaFuncSetAttribute(pass1_kernel,
                         cudaFuncAttributeMaxDynamicSharedMemorySize, SMEM_TOTAL);

    dim3 grid1(MM / MT, BB);
    pass1_kernel<<<grid1, 256, SMEM_TOTAL>>>(memory, keys, strengths, out);
    softmax_kernel<<<BB * HH, 1024>>>(out);
}

// round 4
// speedup vs baseline: 2.4472x; 1.4712x over previous
#include <cuda_runtime.h>
#include <math.h>
#include <stdint.h>

#define BB   32
#define MM   16384
#define WW   256
#define HH   16
#define EPS  1e-5f

#define MT      256
#define KC      32            // cols per chunk
#define NCH     8
#define THREADS 256

#define APITCH 80             // bytes per A-tile row (64B data + 16 pad)
#define BPITCH 528            // bytes per B-tile row (512B data + 16 pad)

// smem byte layout
#define SM_AHI   0            // 256 x 80  = 20480
#define SM_ALO   20480        // 20480
#define SM_BHI   40960        // 16 x 528  = 8448
#define SM_BLO   49408        // 8448
#define SM_SS    57856        // 256 f32
#define SM_KN    58880        // 16 f32
#define SM_SP    58944        // 16 f32
#define SM_TOTAL 59008
#define SHARP_PITCH 264       // f32 pitch for epilogue staging (overlays A tiles)

__device__ __forceinline__ unsigned pack2(float hi_el, float lo_el) {
    unsigned r;
    asm("cvt.rn.satfinite.bf16x2.f32 %0, %1, %2;" : "=r"(r) : "f"(hi_el), "f"(lo_el));
    return r;
}
__device__ __forceinline__ void sts64(unsigned addr, unsigned r0, unsigned r1) {
    asm volatile("st.shared.v2.b32 [%0], {%1, %2};" :: "r"(addr), "r"(r0), "r"(r1)
                 : "memory");
}
__device__ __forceinline__ void ldsm4(unsigned addr, unsigned& r0, unsigned& r1,
                                      unsigned& r2, unsigned& r3) {
    asm volatile("ldmatrix.sync.aligned.m8n8.x4.shared.b16 {%0,%1,%2,%3}, [%4];"
                 : "=r"(r0), "=r"(r1), "=r"(r2), "=r"(r3) : "r"(addr));
}
__device__ __forceinline__ void mma16816(float* d, const unsigned* a,
                                         unsigned b0, unsigned b1) {
    asm volatile(
        "mma.sync.aligned.m16n8k16.row.col.f32.bf16.bf16.f32 "
        "{%0,%1,%2,%3}, {%4,%5,%6,%7}, {%8,%9}, {%0,%1,%2,%3};"
        : "+f"(d[0]), "+f"(d[1]), "+f"(d[2]), "+f"(d[3])
        : "r"(a[0]), "r"(a[1]), "r"(a[2]), "r"(a[3]), "r"(b0), "r"(b1));
}
__device__ __forceinline__ float softplus_f(float x) {
    return fmaxf(x, 0.0f) + log1pf(__expf(-fabsf(x)));
}

__global__ void __launch_bounds__(THREADS, 2)
pass1_kernel(const float* __restrict__ memory,
             const float* __restrict__ keys,
             const float* __restrict__ strengths,
             float* __restrict__ out) {
    extern __shared__ char sm[];
    float* smf = (float*)sm;
    unsigned sb;
    asm("{ .reg .u64 t; cvta.to.shared.u64 t, %1; cvt.u32.u64 %0, t; }"
        : "=r"(sb) : "l"(sm));

    const int tid  = threadIdx.x;
    const int lane = tid & 31;
    const int wid  = tid >> 5;
    const int b    = blockIdx.y;
    const int m0   = blockIdx.x * MT;

    // ---- keys: bf16 hi/lo split into B tiles [h][k], norms, softplus ----
    {
        const float* kb = keys + (size_t)b * HH * WW;
        const int h  = tid >> 4;        // 0..15
        const int cq = tid & 15;        // 16-col group
        float4 kv[4];
        #pragma unroll
        for (int j = 0; j < 4; j++)
            kv[j] = *(const float4*)(kb + h * WW + cq * 16 + j * 4);

        float ss = 0.0f;
        #pragma unroll
        for (int j = 0; j < 4; j++) {
            ss = fmaf(kv[j].x, kv[j].x, ss); ss = fmaf(kv[j].y, kv[j].y, ss);
            ss = fmaf(kv[j].z, kv[j].z, ss); ss = fmaf(kv[j].w, kv[j].w, ss);
        }
        ss += __shfl_xor_sync(0xffffffffu, ss, 1);
        ss += __shfl_xor_sync(0xffffffffu, ss, 2);
        ss += __shfl_xor_sync(0xffffffffu, ss, 4);
        ss += __shfl_xor_sync(0xffffffffu, ss, 8);
        if (cq == 0) {
            smf[SM_KN / 4 + h] = sqrtf(ss + EPS);
            smf[SM_SP / 4 + h] = softplus_f(strengths[b * HH + h]);
        }

        #pragma unroll
        for (int j = 0; j < 4; j++) {
            float4 v = kv[j];
            unsigned hx0 = pack2(v.y, v.x);
            unsigned hx1 = pack2(v.w, v.z);
            float ax = __uint_as_float(hx0 << 16);
            float ay = __uint_as_float(hx0 & 0xffff0000u);
            float az = __uint_as_float(hx1 << 16);
            float aw = __uint_as_float(hx1 & 0xffff0000u);
            unsigned lx0 = pack2(v.y - ay, v.x - ax);
            unsigned lx1 = pack2(v.w - aw, v.z - az);
            unsigned off = h * BPITCH + cq * 32 + j * 8;
            sts64(sb + SM_BHI + off, hx0, hx1);
            sts64(sb + SM_BLO + off, lx0, lx1);
        }
    }

    // ---- main loop ----
    const int arow  = tid >> 3;         // base row for convert (rows arow + 32u)
    const int acol4 = tid & 7;          // float4 col within chunk
    const float* gp = memory + ((size_t)b * MM + m0 + arow) * WW + acol4 * 4;

    float d[2][2][4];
    #pragma unroll
    for (int t = 0; t < 2; t++)
        #pragma unroll
        for (int n = 0; n < 2; n++)
            #pragma unroll
            for (int i = 0; i < 4; i++) d[t][n][i] = 0.0f;

    float ssu[8];
    #pragma unroll
    for (int u = 0; u < 8; u++) ssu[u] = 0.0f;

    // ldmatrix lane addressing precompute
    const int lrow8 = (lane & 7) + ((lane >> 3) & 1) * 8;   // row within 16-block
    const int lk16  = (lane >> 4) * 16;                     // k-half byte offset
    const unsigned a_lane_off = (unsigned)((wid * 32 + lrow8) * APITCH + lk16);
    const unsigned b_lane_off = (unsigned)(lrow8 * BPITCH + lk16);

    float4 v[8];
    #pragma unroll
    for (int u = 0; u < 8; u++)
        v[u] = *(const float4*)(gp + (size_t)(32 * u) * WW);

    for (int c = 0; c < NCH; c++) {
        // convert + STS + row-norm accumulation
        #pragma unroll
        for (int u = 0; u < 8; u++) {
            float4 w = v[u];
            ssu[u] = fmaf(w.x, w.x, ssu[u]);
            ssu[u] = fmaf(w.y, w.y, ssu[u]);
            ssu[u] = fmaf(w.z, w.z, ssu[u]);
            ssu[u] = fmaf(w.w, w.w, ssu[u]);
            unsigned hx0 = pack2(w.y, w.x);
            unsigned hx1 = pack2(w.w, w.z);
            float ax = __uint_as_float(hx0 << 16);
            float ay = __uint_as_float(hx0 & 0xffff0000u);
            float az = __uint_as_float(hx1 << 16);
            float aw = __uint_as_float(hx1 & 0xffff0000u);
            unsigned lx0 = pack2(w.y - ay, w.x - ax);
            unsigned lx1 = pack2(w.w - aw, w.z - az);
            unsigned off = (arow + 32 * u) * APITCH + acol4 * 8;
            sts64(sb + SM_AHI + off, hx0, hx1);
            sts64(sb + SM_ALO + off, lx0, lx1);
        }
        __syncthreads();

        // prefetch next chunk (overlaps mma)
        if (c + 1 < NCH) {
            #pragma unroll
            for (int u = 0; u < 8; u++)
                v[u] = *(const float4*)(gp + (size_t)(32 * u) * WW + (c + 1) * KC);
        }

        // ldsm + mma
        #pragma unroll
        for (int s = 0; s < 2; s++) {
            unsigned bh[4], bl[4];
            unsigned bkoff = (unsigned)(c * 64 + s * 32);
            ldsm4(sb + SM_BHI + b_lane_off + bkoff, bh[0], bh[1], bh[2], bh[3]);
            ldsm4(sb + SM_BLO + b_lane_off + bkoff, bl[0], bl[1], bl[2], bl[3]);
            #pragma unroll
            for (int t = 0; t < 2; t++) {
                unsigned ah[4], al[4];
                unsigned aoff = a_lane_off + (unsigned)(t * 16 * APITCH + s * 32);
                ldsm4(sb + SM_AHI + aoff, ah[0], ah[1], ah[2], ah[3]);
                ldsm4(sb + SM_ALO + aoff, al[0], al[1], al[2], al[3]);
                // n-tile 0 uses {r0, r2}; n-tile 1 uses {r1, r3}
                mma16816(d[t][0], ah, bh[0], bh[2]);
                mma16816(d[t][0], ah, bl[0], bl[2]);
                mma16816(d[t][0], al, bh[0], bh[2]);
                mma16816(d[t][1], ah, bh[1], bh[3]);
                mma16816(d[t][1], ah, bl[1], bl[3]);
                mma16816(d[t][1], al, bh[1], bh[3]);
            }
        }
        __syncthreads();
    }

    // ---- row-norm reduction across the 8 col4 threads ----
    #pragma unroll
    for (int u = 0; u < 8; u++) {
        float s = ssu[u];
        s += __shfl_xor_sync(0xffffffffu, s, 1);
        s += __shfl_xor_sync(0xffffffffu, s, 2);
        s += __shfl_xor_sync(0xffffffffu, s, 4);
        if ((tid & 7) == 0) smf[SM_SS / 4 + arow + 32 * u] = s;
    }
    __syncthreads();

    // ---- sharpen into smem staging (overlays A tiles), then coalesced write ----
    {
        float* sharp = smf;   // [16][SHARP_PITCH]
        #pragma unroll
        for (int t = 0; t < 2; t++) {
            int r_lo = wid * 32 + t * 16 + (lane >> 2);
            int r_hi = r_lo + 8;
            float mn_lo = sqrtf(smf[SM_SS / 4 + r_lo] + EPS);
            float mn_hi = sqrtf(smf[SM_SS / 4 + r_hi] + EPS);
            #pragma unroll
            for (int n = 0; n < 2; n++) {
                int h0 = n * 8 + (lane & 3) * 2;
                int h1 = h0 + 1;
                float sp0 = smf[SM_SP / 4 + h0], kn0 = smf[SM_KN / 4 + h0];
                float sp1 = smf[SM_SP / 4 + h1], kn1 = smf[SM_KN / 4 + h1];
                sharp[h0 * SHARP_PITCH + r_lo] =
                    __fdividef(d[t][n][0] * sp0, fmaf(kn0, mn_lo, EPS));
                sharp[h1 * SHARP_PITCH + r_lo] =
                    __fdividef(d[t][n][1] * sp1, fmaf(kn1, mn_lo, EPS));
                sharp[h0 * SHARP_PITCH + r_hi] =
                    __fdividef(d[t][n][2] * sp0, fmaf(kn0, mn_hi, EPS));
                sharp[h1 * SHARP_PITCH + r_hi] =
                    __fdividef(d[t][n][3] * sp1, fmaf(kn1, mn_hi, EPS));
            }
        }
    }
    __syncthreads();
    {
        const float* sharp = smf;
        float4* o4 = (float4*)out;
        #pragma unroll
        for (int u = 0; u < 4; u++) {
            int f  = tid + 256 * u;     // 1024 float4
            int h  = f >> 6;
            int r4 = f & 63;
            float4 w = *(const float4*)(sharp + h * SHARP_PITCH + r4 * 4);
            o4[(((size_t)b * HH + h) * MM + m0) / 4 + r4] = w;
        }
    }
}

// ---- pass 2: in-place softmax over M per (b,h) row ----
__global__ void __launch_bounds__(1024)
softmax_kernel(float* __restrict__ out) {
    const int row = blockIdx.x;
    float4* p4 = (float4*)(out + (size_t)row * MM);
    const int t = threadIdx.x;
    const int lane = t & 31, wd = t >> 5;

    __shared__ float sdata[32];
    __shared__ float sres;

    float v[16];
    float lmax = -INFINITY;
    #pragma unroll
    for (int i = 0; i < 4; i++) {
        float4 x = p4[t + 1024 * i];
        v[i * 4 + 0] = x.x; v[i * 4 + 1] = x.y;
        v[i * 4 + 2] = x.z; v[i * 4 + 3] = x.w;
        lmax = fmaxf(lmax, fmaxf(fmaxf(x.x, x.y), fmaxf(x.z, x.w)));
    }
    #pragma unroll
    for (int o = 16; o; o >>= 1) lmax = fmaxf(lmax, __shfl_xor_sync(0xffffffffu, lmax, o));
    if (lane == 0) sdata[wd] = lmax;
    __syncthreads();
    if (wd == 0) {
        float x = sdata[lane];
        #pragma unroll
        for (int o = 16; o; o >>= 1) x = fmaxf(x, __shfl_xor_sync(0xffffffffu, x, o));
        if (lane == 0) sres = x;
    }
    __syncthreads();
    float gmax = sres;
    __syncthreads();

    float lsum = 0.0f;
    #pragma unroll
    for (int i = 0; i < 16; i++) {
        float e = __expf(v[i] - gmax);
        v[i] = e;
        lsum += e;
    }
    #pragma unroll
    for (int o = 16; o; o >>= 1) lsum += __shfl_xor_sync(0xffffffffu, lsum, o);
    if (lane == 0) sdata[wd] = lsum;
    __syncthreads();
    if (wd == 0) {
        float x = sdata[lane];
        #pragma unroll
        for (int o = 16; o; o >>= 1) x += __shfl_xor_sync(0xffffffffu, x, o);
        if (lane == 0) sres = x;
    }
    __syncthreads();
    float inv = __fdividef(1.0f, sres);

    #pragma unroll
    for (int i = 0; i < 4; i++) {
        float4 x;
        x.x = v[i * 4 + 0] * inv; x.y = v[i * 4 + 1] * inv;
        x.z = v[i * 4 + 2] * inv; x.w = v[i * 4 + 3] * inv;
        p4[t + 1024 * i] = x;
    }
}

extern "C" void kernel_launch(void* const* d_in, const int* in_sizes, int n_in,
                              void* d_out, int out_size) {
    const float* memory    = (const float*)d_in[0];
    const float* keys      = (const float*)d_in[1];
    const float* strengths = (const float*)d_in[2];
    float* out = (float*)d_out;

    cudaFuncSetAttribute(pass1_kernel,
                         cudaFuncAttributeMaxDynamicSharedMemorySize, SM_TOTAL);

    dim3 grid1(MM / MT, BB);
    pass1_kernel<<<grid1, THREADS, SM_TOTAL>>>(memory, keys, strengths, out);
    softmax_kernel<<<BB * HH, 1024>>>(out);
}

// round 5
// speedup vs baseline: 2.5808x; 1.0546x over previous
#include <cuda_runtime.h>
#include <math.h>
#include <stdint.h>

#define BB   32
#define MM   16384
#define WW   256
#define HH   16
#define EPS  1e-5f

#define MT      256
#define THREADS 256
#define NCHK    16            // 16-col k chunks

// smem byte layout
#define SM_BH    0            // 16 chunks x 4 tiles x 128B = 8192
#define SM_BL    8192         // 8192
#define SM_KN    16384        // 16 f32
#define SM_SP    16448        // 16 f32
#define SM_SHARP 16512        // 16 x 264 f32 = 16896
#define SM_TOTAL 33408
#define SHARP_PITCH 264

__device__ __forceinline__ unsigned pack2(float hi_el, float lo_el) {
    unsigned r;
    asm("cvt.rn.satfinite.bf16x2.f32 %0, %1, %2;" : "=r"(r) : "f"(hi_el), "f"(lo_el));
    return r;
}
__device__ __forceinline__ void ldsm4(unsigned addr, unsigned& r0, unsigned& r1,
                                      unsigned& r2, unsigned& r3) {
    asm volatile("ldmatrix.sync.aligned.m8n8.x4.shared.b16 {%0,%1,%2,%3}, [%4];"
                 : "=r"(r0), "=r"(r1), "=r"(r2), "=r"(r3) : "r"(addr));
}
__device__ __forceinline__ void mma16816(float* d, unsigned a0, unsigned a1,
                                         unsigned a2, unsigned a3,
                                         unsigned b0, unsigned b1) {
    asm volatile(
        "mma.sync.aligned.m16n8k16.row.col.f32.bf16.bf16.f32 "
        "{%0,%1,%2,%3}, {%4,%5,%6,%7}, {%8,%9}, {%0,%1,%2,%3};"
        : "+f"(d[0]), "+f"(d[1]), "+f"(d[2]), "+f"(d[3])
        : "r"(a0), "r"(a1), "r"(a2), "r"(a3), "r"(b0), "r"(b1));
}
__device__ __forceinline__ float softplus_f(float x) {
    return fmaxf(x, 0.0f) + log1pf(__expf(-fabsf(x)));
}
// split float4 into hi/lo bf16x2 pairs: p01=(x,y), p23=(z,w)
__device__ __forceinline__ void split4(float4 v, unsigned& h01, unsigned& h23,
                                       unsigned& l01, unsigned& l23) {
    h01 = pack2(v.y, v.x);
    h23 = pack2(v.w, v.z);
    float ax = __uint_as_float(h01 << 16);
    float ay = __uint_as_float(h01 & 0xffff0000u);
    float az = __uint_as_float(h23 << 16);
    float aw = __uint_as_float(h23 & 0xffff0000u);
    l01 = pack2(v.y - ay, v.x - ax);
    l23 = pack2(v.w - aw, v.z - az);
}

__global__ void __launch_bounds__(THREADS, 2)
pass1_kernel(const float* __restrict__ memory,
             const float* __restrict__ keys,
             const float* __restrict__ strengths,
             float* __restrict__ out) {
    extern __shared__ char sm[];
    float* smf = (float*)sm;
    unsigned sb;
    asm("{ .reg .u64 t; cvta.to.shared.u64 t, %1; cvt.u32.u64 %0, t; }"
        : "=r"(sb) : "l"(sm));

    const int tid  = threadIdx.x;
    const int lane = tid & 31;
    const int wid  = tid >> 5;
    const int b    = blockIdx.y;
    const int m0   = blockIdx.x * MT;

    const int r = lane >> 2;          // fragment row 0..7
    const int c = lane & 3;           // fragment col group

    // A base: rows (wid*32 + r) + {0,8,16,24}, cols chunk*16 + 4c
    const float* ap = memory + ((size_t)b * MM + m0 + wid * 32 + r) * WW + 4 * c;

    // ---- prefetch chunk 0 ----
    float4 v[2][4];
    #pragma unroll
    for (int j = 0; j < 4; j++)
        v[0][j] = *(const float4*)(ap + j * 8 * WW);

    // ---- keys: permuted bf16 hi/lo B tiles + norms + softplus ----
    {
        const int h = tid >> 4;       // 0..15
        const int t = tid & 15;       // chunk
        const float* kp = keys + (size_t)b * HH * WW + h * WW + t * 16;
        float4 kv[4];
        #pragma unroll
        for (int j = 0; j < 4; j++) kv[j] = *(const float4*)(kp + 4 * j);

        float ss = 0.0f;
        #pragma unroll
        for (int j = 0; j < 4; j++) {
            ss = fmaf(kv[j].x, kv[j].x, ss); ss = fmaf(kv[j].y, kv[j].y, ss);
            ss = fmaf(kv[j].z, kv[j].z, ss); ss = fmaf(kv[j].w, kv[j].w, ss);
        }
        ss += __shfl_xor_sync(0xffffffffu, ss, 1);
        ss += __shfl_xor_sync(0xffffffffu, ss, 2);
        ss += __shfl_xor_sync(0xffffffffu, ss, 4);
        ss += __shfl_xor_sync(0xffffffffu, ss, 8);
        if (t == 0) {
            smf[SM_KN / 4 + h] = sqrtf(ss + EPS);
            smf[SM_SP / 4 + h] = softplus_f(strengths[b * HH + h]);
        }

        // tiles per chunk: [0]=(h0-7,k0-7) [1]=(h8-15,k0-7) [2]=(h0-7,k8-15) [3]=(h8-15,k8-15)
        unsigned base = (unsigned)(t * 512 + (h >> 3) * 128 + (h & 7) * 16);
        #pragma unroll
        for (int q = 0; q < 4; q++) {   // actual col quad
            unsigned h01, h23, l01, l23;
            split4(kv[q], h01, h23, l01, l23);
            // logical pair q of half0 = actual (4q,4q+1); half1 = actual (4q+2,4q+3)
            *(unsigned*)(sm + SM_BH + base + q * 4)       = h01;
            *(unsigned*)(sm + SM_BH + base + 256 + q * 4) = h23;
            *(unsigned*)(sm + SM_BL + base + q * 4)       = l01;
            *(unsigned*)(sm + SM_BL + base + 256 + q * 4) = l23;
        }
    }
    __syncthreads();

    // ---- main loop: no barriers, warps independent ----
    float d[2][2][4];
    #pragma unroll
    for (int mt = 0; mt < 2; mt++)
        #pragma unroll
        for (int nt = 0; nt < 2; nt++)
            #pragma unroll
            for (int i = 0; i < 4; i++) d[mt][nt][i] = 0.0f;

    float ss4[4] = {0.0f, 0.0f, 0.0f, 0.0f};

    const unsigned bl_off = (unsigned)((lane >> 3) * 128 + (lane & 7) * 16);

    #pragma unroll 2
    for (int t = 0; t < NCHK; t++) {
        const int cur = t & 1;
        // prefetch next chunk
        if (t + 1 < NCHK) {
            #pragma unroll
            for (int j = 0; j < 4; j++)
                v[cur ^ 1][j] = *(const float4*)(ap + j * 8 * WW + (t + 1) * 16);
        }

        // B fragments
        unsigned bh[4], bl[4];
        ldsm4(sb + SM_BH + bl_off + t * 512, bh[0], bh[1], bh[2], bh[3]);
        ldsm4(sb + SM_BL + bl_off + t * 512, bl[0], bl[1], bl[2], bl[3]);

        // convert + norms
        unsigned ah01[4], ah23[4], al01[4], al23[4];
        #pragma unroll
        for (int j = 0; j < 4; j++) {
            float4 w = v[cur][j];
            ss4[j] = fmaf(w.x, w.x, ss4[j]);
            ss4[j] = fmaf(w.y, w.y, ss4[j]);
            ss4[j] = fmaf(w.z, w.z, ss4[j]);
            ss4[j] = fmaf(w.w, w.w, ss4[j]);
            split4(w, ah01[j], ah23[j], al01[j], al23[j]);
        }

        // tile0 = rows (v0, v1), tile1 = rows (v2, v3)
        #pragma unroll
        for (int mt = 0; mt < 2; mt++) {
            int j0 = mt * 2, j1 = mt * 2 + 1;
            // n-tile0 uses {bh[0], bh[2]}, n-tile1 uses {bh[1], bh[3]}
            mma16816(d[mt][0], ah01[j0], ah01[j1], ah23[j0], ah23[j1], bh[0], bh[2]);
            mma16816(d[mt][0], ah01[j0], ah01[j1], ah23[j0], ah23[j1], bl[0], bl[2]);
            mma16816(d[mt][0], al01[j0], al01[j1], al23[j0], al23[j1], bh[0], bh[2]);
            mma16816(d[mt][1], ah01[j0], ah01[j1], ah23[j0], ah23[j1], bh[1], bh[3]);
            mma16816(d[mt][1], ah01[j0], ah01[j1], ah23[j0], ah23[j1], bl[1], bl[3]);
            mma16816(d[mt][1], al01[j0], al01[j1], al23[j0], al23[j1], bh[1], bh[3]);
        }
    }

    // ---- row norms: reduce across the 4-lane col group (rows identical there) ----
    #pragma unroll
    for (int j = 0; j < 4; j++) {
        ss4[j] += __shfl_xor_sync(0xffffffffu, ss4[j], 1);
        ss4[j] += __shfl_xor_sync(0xffffffffu, ss4[j], 2);
        ss4[j] = sqrtf(ss4[j] + EPS);    // now = mem norm of row (wid*32 + r + 8j)
    }

    // ---- sharpen into smem staging ----
    {
        float* sharp = smf + SM_SHARP / 4;
        #pragma unroll
        for (int nt = 0; nt < 2; nt++) {
            int h0 = nt * 8 + 2 * c;
            float sp0 = smf[SM_SP / 4 + h0],     kn0 = smf[SM_KN / 4 + h0];
            float sp1 = smf[SM_SP / 4 + h0 + 1], kn1 = smf[SM_KN / 4 + h0 + 1];
            #pragma unroll
            for (int mt = 0; mt < 2; mt++) {
                int row_lo = wid * 32 + 16 * mt + r;
                float mn_lo = ss4[2 * mt];
                float mn_hi = ss4[2 * mt + 1];
                sharp[h0 * SHARP_PITCH + row_lo] =
                    __fdividef(d[mt][nt][0] * sp0, fmaf(kn0, mn_lo, EPS));
                sharp[(h0 + 1) * SHARP_PITCH + row_lo] =
                    __fdividef(d[mt][nt][1] * sp1, fmaf(kn1, mn_lo, EPS));
                sharp[h0 * SHARP_PITCH + row_lo + 8] =
                    __fdividef(d[mt][nt][2] * sp0, fmaf(kn0, mn_hi, EPS));
                sharp[(h0 + 1) * SHARP_PITCH + row_lo + 8] =
                    __fdividef(d[mt][nt][3] * sp1, fmaf(kn1, mn_hi, EPS));
            }
        }
    }
    __syncthreads();

    // ---- coalesced write ----
    {
        const float* sharp = smf + SM_SHARP / 4;
        float4* o4 = (float4*)out;
        #pragma unroll
        for (int u = 0; u < 4; u++) {
            int f  = tid + 256 * u;     // 1024 float4
            int h  = f >> 6;
            int r4 = f & 63;
            float4 w = *(const float4*)(sharp + h * SHARP_PITCH + r4 * 4);
            o4[(((size_t)b * HH + h) * MM + m0) / 4 + r4] = w;
        }
    }
}

// ---- pass 2: in-place softmax over M per (b,h) row ----
__global__ void __launch_bounds__(1024)
softmax_kernel(float* __restrict__ out) {
    const int row = blockIdx.x;
    float4* p4 = (float4*)(out + (size_t)row * MM);
    const int t = threadIdx.x;
    const int lane = t & 31, wd = t >> 5;

    __shared__ float sdata[32];
    __shared__ float sres;

    float v[16];
    float lmax = -INFINITY;
    #pragma unroll
    for (int i = 0; i < 4; i++) {
        float4 x = p4[t + 1024 * i];
        v[i * 4 + 0] = x.x; v[i * 4 + 1] = x.y;
        v[i * 4 + 2] = x.z; v[i * 4 + 3] = x.w;
        lmax = fmaxf(lmax, fmaxf(fmaxf(x.x, x.y), fmaxf(x.z, x.w)));
    }
    #pragma unroll
    for (int o = 16; o; o >>= 1) lmax = fmaxf(lmax, __shfl_xor_sync(0xffffffffu, lmax, o));
    if (lane == 0) sdata[wd] = lmax;
    __syncthreads();
    if (wd == 0) {
        float x = sdata[lane];
        #pragma unroll
        for (int o = 16; o; o >>= 1) x = fmaxf(x, __shfl_xor_sync(0xffffffffu, x, o));
        if (lane == 0) sres = x;
    }
    __syncthreads();
    float gmax = sres;
    __syncthreads();

    float lsum = 0.0f;
    #pragma unroll
    for (int i = 0; i < 16; i++) {
        float e = __expf(v[i] - gmax);
        v[i] = e;
        lsum += e;
    }
    #pragma unroll
    for (int o = 16; o; o >>= 1) lsum += __shfl_xor_sync(0xffffffffu, lsum, o);
    if (lane == 0) sdata[wd] = lsum;
    __syncthreads();
    if (wd == 0) {
        float x = sdata[lane];
        #pragma unroll
        for (int o = 16; o; o >>= 1) x += __shfl_xor_sync(0xffffffffu, x, o);
        if (lane == 0) sres = x;
    }
    __syncthreads();
    float inv = __fdividef(1.0f, sres);

    #pragma unroll
    for (int i = 0; i < 4; i++) {
        float4 x;
        x.x = v[i * 4 + 0] * inv; x.y = v[i * 4 + 1] * inv;
        x.z = v[i * 4 + 2] * inv; x.w = v[i * 4 + 3] * inv;
        p4[t + 1024 * i] = x;
    }
}

extern "C" void kernel_launch(void* const* d_in, const int* in_sizes, int n_in,
                              void* d_out, int out_size) {
    const float* memory    = (const float*)d_in[0];
    const float* keys      = (const float*)d_in[1];
    const float* strengths = (const float*)d_in[2];
    float* out = (float*)d_out;

    cudaFuncSetAttribute(pass1_kernel,
                         cudaFuncAttributeMaxDynamicSharedMemorySize, SM_TOTAL);

    dim3 grid1(MM / MT, BB);
    pass1_kernel<<<grid1, THREADS, SM_TOTAL>>>(memory, keys, strengths, out);
    softmax_kernel<<<BB * HH, 1024>>>(out);
}

// round 6
// speedup vs baseline: 2.8157x; 1.0910x over previous
#include <cuda_runtime.h>
#include <math.h>
#include <stdint.h>

#define BB   32
#define MM   16384
#define WW   256
#define HH   16
#define EPS  1e-5f

#define MT      256
#define THREADS 256
#define NCHK    16            // 16-col k chunks
#define DEPTH   4             // cp.async stages per warp

// smem byte layout
#define SM_A     0            // 8 warps x 4 stages x 2048B = 65536
#define SM_BH    65536        // 16 chunks x 4 tiles x 128B = 8192
#define SM_BL    73728        // 8192
#define SM_KN    81920        // 16 f32
#define SM_SP    81984        // 16 f32
#define SM_TOTAL 82048
// sharp staging overlays SM_A after the main loop (16 x 264 f32 = 16896B)
#define SHARP_PITCH 264

__device__ __forceinline__ unsigned pack2(float hi_el, float lo_el) {
    unsigned r;
    asm("cvt.rn.satfinite.bf16x2.f32 %0, %1, %2;" : "=r"(r) : "f"(hi_el), "f"(lo_el));
    return r;
}
__device__ __forceinline__ void ldsm4(unsigned addr, unsigned& r0, unsigned& r1,
                                      unsigned& r2, unsigned& r3) {
    asm volatile("ldmatrix.sync.aligned.m8n8.x4.shared.b16 {%0,%1,%2,%3}, [%4];"
                 : "=r"(r0), "=r"(r1), "=r"(r2), "=r"(r3) : "r"(addr));
}
__device__ __forceinline__ void mma16816(float* d, unsigned a0, unsigned a1,
                                         unsigned a2, unsigned a3,
                                         unsigned b0, unsigned b1) {
    asm volatile(
        "mma.sync.aligned.m16n8k16.row.col.f32.bf16.bf16.f32 "
        "{%0,%1,%2,%3}, {%4,%5,%6,%7}, {%8,%9}, {%0,%1,%2,%3};"
        : "+f"(d[0]), "+f"(d[1]), "+f"(d[2]), "+f"(d[3])
        : "r"(a0), "r"(a1), "r"(a2), "r"(a3), "r"(b0), "r"(b1));
}
__device__ __forceinline__ void cp_async16(unsigned smem_addr, const void* gptr) {
    asm volatile("cp.async.cg.shared.global [%0], [%1], 16;"
                 :: "r"(smem_addr), "l"(gptr));
}
__device__ __forceinline__ void cp_commit() {
    asm volatile("cp.async.commit_group;");
}
__device__ __forceinline__ void cp_wait3() {
    asm volatile("cp.async.wait_group 3;");
}
__device__ __forceinline__ float4 lds128(unsigned addr) {
    float4 v;
    asm volatile("ld.shared.v4.f32 {%0,%1,%2,%3}, [%4];"
                 : "=f"(v.x), "=f"(v.y), "=f"(v.z), "=f"(v.w) : "r"(addr));
    return v;
}
__device__ __forceinline__ float softplus_f(float x) {
    return fmaxf(x, 0.0f) + log1pf(__expf(-fabsf(x)));
}
// split float4 into hi/lo bf16x2 pairs: p01=(x,y), p23=(z,w)
__device__ __forceinline__ void split4(float4 v, unsigned& h01, unsigned& h23,
                                       unsigned& l01, unsigned& l23) {
    h01 = pack2(v.y, v.x);
    h23 = pack2(v.w, v.z);
    float ax = __uint_as_float(h01 << 16);
    float ay = __uint_as_float(h01 & 0xffff0000u);
    float az = __uint_as_float(h23 << 16);
    float aw = __uint_as_float(h23 & 0xffff0000u);
    l01 = pack2(v.y - ay, v.x - ax);
    l23 = pack2(v.w - aw, v.z - az);
}

__global__ void __launch_bounds__(THREADS, 2)
pass1_kernel(const float* __restrict__ memory,
             const float* __restrict__ keys,
             const float* __restrict__ strengths,
             float* __restrict__ out) {
    extern __shared__ char sm[];
    float* smf = (float*)sm;
    unsigned sb;
    asm("{ .reg .u64 t; cvta.to.shared.u64 t, %1; cvt.u32.u64 %0, t; }"
        : "=r"(sb) : "l"(sm));

    const int tid  = threadIdx.x;
    const int lane = tid & 31;
    const int wid  = tid >> 5;
    const int b    = blockIdx.y;
    const int m0   = blockIdx.x * MT;

    const int r = lane >> 2;          // fragment row 0..7
    const int c = lane & 3;           // fragment col group

    // A source: rows (wid*32 + r) + {0,8,16,24}, cols chunk*16 + 4c
    const float* ap = memory + ((size_t)b * MM + m0 + wid * 32 + r) * WW + 4 * c;
    // per-warp smem ring; each lane copies/reads its own 16B
    const unsigned aring = sb + SM_A + wid * (DEPTH * 2048) + lane * 16;

    // ---- prologue: issue stages 0..2 ----
    #pragma unroll
    for (int s = 0; s < DEPTH - 1; s++) {
        #pragma unroll
        for (int j = 0; j < 4; j++)
            cp_async16(aring + s * 2048 + j * 512, ap + (size_t)j * 8 * WW + s * 16);
        cp_commit();
    }

    // ---- keys: permuted bf16 hi/lo B tiles + norms + softplus ----
    {
        const int h = tid >> 4;       // 0..15
        const int t = tid & 15;       // chunk
        const float* kp = keys + (size_t)b * HH * WW + h * WW + t * 16;
        float4 kv[4];
        #pragma unroll
        for (int j = 0; j < 4; j++) kv[j] = *(const float4*)(kp + 4 * j);

        float ss = 0.0f;
        #pragma unroll
        for (int j = 0; j < 4; j++) {
            ss = fmaf(kv[j].x, kv[j].x, ss); ss = fmaf(kv[j].y, kv[j].y, ss);
            ss = fmaf(kv[j].z, kv[j].z, ss); ss = fmaf(kv[j].w, kv[j].w, ss);
        }
        ss += __shfl_xor_sync(0xffffffffu, ss, 1);
        ss += __shfl_xor_sync(0xffffffffu, ss, 2);
        ss += __shfl_xor_sync(0xffffffffu, ss, 4);
        ss += __shfl_xor_sync(0xffffffffu, ss, 8);
        if (t == 0) {
            smf[SM_KN / 4 + h] = sqrtf(ss + EPS);
            smf[SM_SP / 4 + h] = softplus_f(strengths[b * HH + h]);
        }

        // tiles per chunk: [0]=(h0-7,k0-7) [1]=(h8-15,k0-7) [2]=(h0-7,k8-15) [3]=(h8-15,k8-15)
        unsigned base = (unsigned)(t * 512 + (h >> 3) * 128 + (h & 7) * 16);
        #pragma unroll
        for (int q = 0; q < 4; q++) {   // actual col quad
            unsigned h01, h23, l01, l23;
            split4(kv[q], h01, h23, l01, l23);
            *(unsigned*)(sm + SM_BH + base + q * 4)       = h01;
            *(unsigned*)(sm + SM_BH + base + 256 + q * 4) = h23;
            *(unsigned*)(sm + SM_BL + base + q * 4)       = l01;
            *(unsigned*)(sm + SM_BL + base + 256 + q * 4) = l23;
        }
    }
    __syncthreads();

    // ---- main loop: per-warp cp.async pipeline, no barriers ----
    float d[2][2][4];
    #pragma unroll
    for (int mt = 0; mt < 2; mt++)
        #pragma unroll
        for (int nt = 0; nt < 2; nt++)
            #pragma unroll
            for (int i = 0; i < 4; i++) d[mt][nt][i] = 0.0f;

    float ss4[4] = {0.0f, 0.0f, 0.0f, 0.0f};

    const unsigned bl_off = (unsigned)((lane >> 3) * 128 + (lane & 7) * 16);

    for (int t = 0; t < NCHK; t++) {
        // issue chunk t+3 (or empty commit to keep group count uniform)
        if (t + DEPTH - 1 < NCHK) {
            unsigned dst = aring + ((t + DEPTH - 1) & (DEPTH - 1)) * 2048;
            #pragma unroll
            for (int j = 0; j < 4; j++)
                cp_async16(dst + j * 512,
                           ap + (size_t)j * 8 * WW + (t + DEPTH - 1) * 16);
        }
        cp_commit();
        cp_wait3();            // chunk t's group complete

        // B fragments
        unsigned bh[4], bl[4];
        ldsm4(sb + SM_BH + bl_off + t * 512, bh[0], bh[1], bh[2], bh[3]);
        ldsm4(sb + SM_BL + bl_off + t * 512, bl[0], bl[1], bl[2], bl[3]);

        // A from own ring slot + convert + norms
        const unsigned src = aring + (t & (DEPTH - 1)) * 2048;
        unsigned ah01[4], ah23[4], al01[4], al23[4];
        #pragma unroll
        for (int j = 0; j < 4; j++) {
            float4 w = lds128(src + j * 512);
            ss4[j] = fmaf(w.x, w.x, ss4[j]);
            ss4[j] = fmaf(w.y, w.y, ss4[j]);
            ss4[j] = fmaf(w.z, w.z, ss4[j]);
            ss4[j] = fmaf(w.w, w.w, ss4[j]);
            split4(w, ah01[j], ah23[j], al01[j], al23[j]);
        }

        // tile0 = rows (v0, v1), tile1 = rows (v2, v3)
        #pragma unroll
        for (int mt = 0; mt < 2; mt++) {
            int j0 = mt * 2, j1 = mt * 2 + 1;
            mma16816(d[mt][0], ah01[j0], ah01[j1], ah23[j0], ah23[j1], bh[0], bh[2]);
            mma16816(d[mt][0], ah01[j0], ah01[j1], ah23[j0], ah23[j1], bl[0], bl[2]);
            mma16816(d[mt][0], al01[j0], al01[j1], al23[j0], al23[j1], bh[0], bh[2]);
            mma16816(d[mt][1], ah01[j0], ah01[j1], ah23[j0], ah23[j1], bh[1], bh[3]);
            mma16816(d[mt][1], ah01[j0], ah01[j1], ah23[j0], ah23[j1], bl[1], bl[3]);
            mma16816(d[mt][1], al01[j0], al01[j1], al23[j0], al23[j1], bh[1], bh[3]);
        }
    }

    // ---- row norms: reduce across the 4-lane col group ----
    #pragma unroll
    for (int j = 0; j < 4; j++) {
        ss4[j] += __shfl_xor_sync(0xffffffffu, ss4[j], 1);
        ss4[j] += __shfl_xor_sync(0xffffffffu, ss4[j], 2);
        ss4[j] = sqrtf(ss4[j] + EPS);    // mem norm of row (wid*32 + 16*(j>>1) + r + 8*(j&1))
    }

    __syncthreads();   // all warps done with A ring before sharp overlays it

    // ---- sharpen into smem staging (overlays A ring) ----
    {
        float* sharp = smf;   // [16][SHARP_PITCH]
        #pragma unroll
        for (int nt = 0; nt < 2; nt++) {
            int h0 = nt * 8 + 2 * c;
            float sp0 = smf[SM_SP / 4 + h0],     kn0 = smf[SM_KN / 4 + h0];
            float sp1 = smf[SM_SP / 4 + h0 + 1], kn1 = smf[SM_KN / 4 + h0 + 1];
            #pragma unroll
            for (int mt = 0; mt < 2; mt++) {
                int row_lo = wid * 32 + 16 * mt + r;
                float mn_lo = ss4[2 * mt];
                float mn_hi = ss4[2 * mt + 1];
                sharp[h0 * SHARP_PITCH + row_lo] =
                    __fdividef(d[mt][nt][0] * sp0, fmaf(kn0, mn_lo, EPS));
                sharp[(h0 + 1) * SHARP_PITCH + row_lo] =
                    __fdividef(d[mt][nt][1] * sp1, fmaf(kn1, mn_lo, EPS));
                sharp[h0 * SHARP_PITCH + row_lo + 8] =
                    __fdividef(d[mt][nt][2] * sp0, fmaf(kn0, mn_hi, EPS));
                sharp[(h0 + 1) * SHARP_PITCH + row_lo + 8] =
                    __fdividef(d[mt][nt][3] * sp1, fmaf(kn1, mn_hi, EPS));
            }
        }
    }
    __syncthreads();

    // ---- coalesced write ----
    {
        const float* sharp = smf;
        float4* o4 = (float4*)out;
        #pragma unroll
        for (int u = 0; u < 4; u++) {
            int f  = tid + 256 * u;     // 1024 float4
            int h  = f >> 6;
            int r4 = f & 63;
            float4 w = *(const float4*)(sharp + h * SHARP_PITCH + r4 * 4);
            o4[(((size_t)b * HH + h) * MM + m0) / 4 + r4] = w;
        }
    }
}

// ---- pass 2: in-place softmax over M per (b,h) row ----
__global__ void __launch_bounds__(1024)
softmax_kernel(float* __restrict__ out) {
    const int row = blockIdx.x;
    float4* p4 = (float4*)(out + (size_t)row * MM);
    const int t = threadIdx.x;
    const int lane = t & 31, wd = t >> 5;

    __shared__ float sdata[32];
    __shared__ float sres;

    float v[16];
    float lmax = -INFINITY;
    #pragma unroll
    for (int i = 0; i < 4; i++) {
        float4 x = p4[t + 1024 * i];
        v[i * 4 + 0] = x.x; v[i * 4 + 1] = x.y;
        v[i * 4 + 2] = x.z; v[i * 4 + 3] = x.w;
        lmax = fmaxf(lmax, fmaxf(fmaxf(x.x, x.y), fmaxf(x.z, x.w)));
    }
    #pragma unroll
    for (int o = 16; o; o >>= 1) lmax = fmaxf(lmax, __shfl_xor_sync(0xffffffffu, lmax, o));
    if (lane == 0) sdata[wd] = lmax;
    __syncthreads();
    if (wd == 0) {
        float x = sdata[lane];
        #pragma unroll
        for (int o = 16; o; o >>= 1) x = fmaxf(x, __shfl_xor_sync(0xffffffffu, x, o));
        if (lane == 0) sres = x;
    }
    __syncthreads();
    float gmax = sres;
    __syncthreads();

    float lsum = 0.0f;
    #pragma unroll
    for (int i = 0; i < 16; i++) {
        float e = __expf(v[i] - gmax);
        v[i] = e;
        lsum += e;
    }
    #pragma unroll
    for (int o = 16; o; o >>= 1) lsum += __shfl_xor_sync(0xffffffffu, lsum, o);
    if (lane == 0) sdata[wd] = lsum;
    __syncthreads();
    if (wd == 0) {
        float x = sdata[lane];
        #pragma unroll
        for (int o = 16; o; o >>= 1) x += __shfl_xor_sync(0xffffffffu, x, o);
        if (lane == 0) sres = x;
    }
    __syncthreads();
    float inv = __fdividef(1.0f, sres);

    #pragma unroll
    for (int i = 0; i < 4; i++) {
        float4 x;
        x.x = v[i * 4 + 0] * inv; x.y = v[i * 4 + 1] * inv;
        x.z = v[i * 4 + 2] * inv; x.w = v[i * 4 + 3] * inv;
        p4[t + 1024 * i] = x;
    }
}

extern "C" void kernel_launch(void* const* d_in, const int* in_sizes, int n_in,
                              void* d_out, int out_size) {
    const float* memory    = (const float*)d_in[0];
    const float* keys      = (const float*)d_in[1];
    const float* strengths = (const float*)d_in[2];
    float* out = (float*)d_out;

    cudaFuncSetAttribute(pass1_kernel,
                         cudaFuncAttributeMaxDynamicSharedMemorySize, SM_TOTAL);

    dim3 grid1(MM / MT, BB);
    pass1_kernel<<<grid1, THREADS, SM_TOTAL>>>(memory, keys, strengths, out);
    softmax_kernel<<<BB * HH, 1024>>>(out);
}